// round 11
// baseline (speedup 1.0000x reference)
#include <cuda_runtime.h>
#include <cuda_bf16.h>
#include <cstdint>

#define VOCAB   1000000
#define EMB     50
#define OUTD    2
#define BATCH   128
#define SEQ     2000

#define HALF    (SEQ / 2)           // 1000 tokens per CTA
#define NWARPS  32                  // 1024 threads per block
#define NTHREADS (NWARPS * 32)

// ---------------------------------------------------------------------------
// Cluster of 2 CTAs per batch row; each CTA pools 1000 tokens.
// Rank 1 sends its projected partial (d0,d1) to rank 0 via DSMEM;
// rank 0 combines and writes the 2 outputs. grid = 256 CTAs -> 2 CTAs/SM.
// ---------------------------------------------------------------------------
__global__ __launch_bounds__(NTHREADS) __cluster_dims__(2, 1, 1)
void fused_cluster_kernel(const int* __restrict__ t,
                          const float* __restrict__ emb,
                          const float* __restrict__ W,
                          const float* __restrict__ bias,
                          float* __restrict__ out)
{
    const int b    = blockIdx.x >> 1;
    const int half = blockIdx.x & 1;
    const int tid  = threadIdx.x;
    const int wid  = tid >> 5;
    const int lane = tid & 31;

    uint32_t rank;
    asm("mov.u32 %0, %%cluster_ctarank;" : "=r"(rank));

    __shared__ int      sidx[HALF];           // 4 KB
    __shared__ float2   sred[NWARPS][25];     // 6.4 KB
    __shared__ uint64_t s_peer;               // rank1 -> rank0 partial

    // Stage this half-row's 1000 indices (coalesced).
    const int* tp = t + (size_t)b * SEQ + (size_t)half * HALF;
    if (tid < HALF) sidx[tid] = tp[tid];
    __syncthreads();

    const float2* __restrict__ emb2 = (const float2*)emb;

    float2 acc = make_float2(0.0f, 0.0f);
    if (lane < 25) {
        #pragma unroll 8
        for (int i = wid; i < HALF; i += NWARPS) {   // ~31 tokens per warp
            int idx = sidx[i];
            if (idx >= 0 && idx < VOCAB) {
                float2 v = __ldg(&emb2[(size_t)idx * 25 + lane]);
                acc.x += v.x;
                acc.y += v.y;
            }
        }
        sred[wid][lane] = acc;
    }
    __syncthreads();

    // Warp 0: reduce 32 warp partials, project onto the two W rows.
    float d0 = 0.0f, d1 = 0.0f;
    if (tid < 32) {
        if (tid < 25) {
            float2 p = make_float2(0.0f, 0.0f);
            #pragma unroll
            for (int w = 0; w < NWARPS; w++) {
                p.x += sred[w][tid].x;
                p.y += sred[w][tid].y;
            }
            d0 = p.x * W[2 * tid]       + p.y * W[2 * tid + 1];       // W row 0
            d1 = p.x * W[EMB + 2 * tid] + p.y * W[EMB + 2 * tid + 1]; // W row 1
        }
        #pragma unroll
        for (int off = 16; off > 0; off >>= 1) {
            d0 += __shfl_down_sync(0xFFFFFFFFu, d0, off);
            d1 += __shfl_down_sync(0xFFFFFFFFu, d1, off);
        }
    }

    // Rank 1 -> rank 0: ship packed (d0,d1) into rank 0's s_peer via DSMEM.
    if (rank == 1 && tid == 0) {
        uint32_t laddr;
        asm("{ .reg .u64 a; cvta.to.shared.u64 a, %1; cvt.u32.u64 %0, a; }"
            : "=r"(laddr) : "l"(&s_peer));
        uint32_t raddr;
        asm volatile("mapa.shared::cluster.u32 %0, %1, %2;"
                     : "=r"(raddr) : "r"(laddr), "r"(0));
        uint64_t pkt;
        asm("mov.b64 %0, {%1, %2};" : "=l"(pkt) : "f"(d0), "f"(d1));
        asm volatile("st.shared::cluster.u64 [%0], %1;"
                     :: "r"(raddr), "l"(pkt) : "memory");
    }

    // Cluster barrier: release rank1's DSMEM store, acquire on rank0.
    asm volatile("barrier.cluster.arrive.aligned;" ::: "memory");
    asm volatile("barrier.cluster.wait.aligned;" ::: "memory");

    if (rank == 0 && tid == 0) {
        float p0, p1;
        asm("mov.b64 {%0, %1}, %2;" : "=f"(p0), "=f"(p1) : "l"(s_peer));
        const float inv = 1.0f / (float)BATCH;
        out[b * OUTD + 0] = fmaxf((d0 + p0) * inv + bias[0], 0.0f);
        out[b * OUTD + 1] = fmaxf((d1 + p1) * inv + bias[1], 0.0f);
    }
}

// ---------------------------------------------------------------------------
// Inputs: t [128,2000] int32, embeddings [1e6,50] f32, W [2,50] f32, b [2] f32.
// Output: [128,2] f32.
// ---------------------------------------------------------------------------
extern "C" void kernel_launch(void* const* d_in, const int* in_sizes, int n_in,
                              void* d_out, int out_size)
{
    const int*   t   = (const int*)d_in[0];
    const float* emb = (const float*)d_in[1];
    const float* W   = (const float*)d_in[2];
    const float* bia = (const float*)d_in[3];
    float*       out = (float*)d_out;

    fused_cluster_kernel<<<BATCH * 2, NTHREADS>>>(t, emb, W, bia, out);
}

// round 13
// speedup vs baseline: 1.0858x; 1.0858x over previous
#include <cuda_runtime.h>
#include <cuda_bf16.h>
#include <cstdint>

#define VOCAB   1000000
#define EMB     50
#define OUTD    2
#define BATCH   128
#define SEQ     2000

#define HALF    (SEQ / 2)           // 1000 tokens per CTA
#define NWARPS  32                  // 1024 threads per block
#define NTHREADS (NWARPS * 32)

// Pairwise handoff: half-1 CTA publishes its projected partial for row b.
__device__ float2       g_part[BATCH];
__device__ unsigned int g_flag[BATCH];   // zero-initialized

// ---------------------------------------------------------------------------
// 256 independent CTAs, one per half batch-row (2 resident CTAs/SM).
// Each CTA pools 1000 tokens and projects to (d0,d1).
// half==1: release-store partial + flag.   half==0: acquire-spin on partner,
// combine, /BATCH + bias + ReLU, write output, reset flag for next replay.
// ---------------------------------------------------------------------------
__global__ __launch_bounds__(NTHREADS)
void fused_pair_kernel(const int* __restrict__ t,
                       const float* __restrict__ emb,
                       const float* __restrict__ W,
                       const float* __restrict__ bias,
                       float* __restrict__ out)
{
    const int b    = blockIdx.x >> 1;
    const int half = blockIdx.x & 1;
    const int tid  = threadIdx.x;
    const int wid  = tid >> 5;
    const int lane = tid & 31;

    __shared__ int    sidx[HALF];            // 4 KB
    __shared__ float2 sred[NWARPS][25];      // 6.4 KB

    // Stage this half-row's 1000 indices (coalesced).
    const int* tp = t + (size_t)b * SEQ + (size_t)half * HALF;
    if (tid < HALF) sidx[tid] = tp[tid];
    __syncthreads();

    const float2* __restrict__ emb2 = (const float2*)emb;

    float2 acc = make_float2(0.0f, 0.0f);
    if (lane < 25) {
        #pragma unroll 16
        for (int i = wid; i < HALF; i += NWARPS) {   // ~31 tokens per warp
            int idx = sidx[i];
            if (idx >= 0 && idx < VOCAB) {
                float2 v = __ldg(&emb2[(size_t)idx * 25 + lane]);
                acc.x += v.x;
                acc.y += v.y;
            }
        }
        sred[wid][lane] = acc;
    }
    __syncthreads();

    // Warp 0: reduce 32 warp partials, project onto the two W rows.
    if (tid < 32) {
        float d0 = 0.0f, d1 = 0.0f;
        if (tid < 25) {
            float2 p = make_float2(0.0f, 0.0f);
            #pragma unroll
            for (int w = 0; w < NWARPS; w++) {
                p.x += sred[w][tid].x;
                p.y += sred[w][tid].y;
            }
            d0 = p.x * W[2 * tid]       + p.y * W[2 * tid + 1];       // W row 0
            d1 = p.x * W[EMB + 2 * tid] + p.y * W[EMB + 2 * tid + 1]; // W row 1
        }
        #pragma unroll
        for (int off = 16; off > 0; off >>= 1) {
            d0 += __shfl_down_sync(0xFFFFFFFFu, d0, off);
            d1 += __shfl_down_sync(0xFFFFFFFFu, d1, off);
        }

        if (tid == 0) {
            if (half == 1) {
                // Publish partial, then release-store the flag.
                asm volatile("st.global.v2.f32 [%0], {%1, %2};"
                             :: "l"(&g_part[b]), "f"(d0), "f"(d1) : "memory");
                asm volatile("st.global.release.gpu.u32 [%0], %1;"
                             :: "l"(&g_flag[b]), "r"(1u) : "memory");
            } else {
                // Acquire-spin on the partner's flag (partner is co-resident:
                // full grid fits at 2 CTAs/SM, so no deadlock).
                unsigned int f;
                do {
                    asm volatile("ld.global.acquire.gpu.u32 %0, [%1];"
                                 : "=r"(f) : "l"(&g_flag[b]) : "memory");
                } while (f == 0u);

                float p0, p1;
                asm volatile("ld.global.v2.f32 {%0, %1}, [%2];"
                             : "=f"(p0), "=f"(p1) : "l"(&g_part[b]) : "memory");

                const float inv = 1.0f / (float)BATCH;
                out[b * OUTD + 0] = fmaxf((d0 + p0) * inv + bias[0], 0.0f);
                out[b * OUTD + 1] = fmaxf((d1 + p1) * inv + bias[1], 0.0f);

                // Reset for the next graph replay (launches are serialized).
                g_flag[b] = 0u;
            }
        }
    }
}

// ---------------------------------------------------------------------------
// Inputs: t [128,2000] int32, embeddings [1e6,50] f32, W [2,50] f32, b [2] f32.
// Output: [128,2] f32.
// ---------------------------------------------------------------------------
extern "C" void kernel_launch(void* const* d_in, const int* in_sizes, int n_in,
                              void* d_out, int out_size)
{
    const int*   t   = (const int*)d_in[0];
    const float* emb = (const float*)d_in[1];
    const float* W   = (const float*)d_in[2];
    const float* bia = (const float*)d_in[3];
    float*       out = (float*)d_out;

    fused_pair_kernel<<<BATCH * 2, NTHREADS>>>(t, emb, W, bia, out);
}

// round 14
// speedup vs baseline: 1.2004x; 1.1056x over previous
#include <cuda_runtime.h>
#include <cuda_bf16.h>
#include <cstdint>

#define VOCAB   1000000
#define EMB     50
#define OUTD    2
#define BATCH   128
#define SEQ     2000

#define NCHUNK  25                   // blocks per batch row
#define TOK     (SEQ / NCHUNK)       // 80 tokens per block
#define WARPS   8                    // 256 threads
#define TOK_PER_WARP (TOK / WARPS)   // 10

// Per-row partials: g_dots[b][chunk] = (d0,d1). Row = 200 B contiguous.
__device__ float2       g_dots[BATCH][NCHUNK];
// Arrival counters, padded to 32 B to avoid atomic line contention.
__device__ unsigned int g_cnt[BATCH * 8];    // use index b*8; zero-initialized

// ---------------------------------------------------------------------------
// R5's proven gather shape: grid=(BATCH, NCHUNK), block=256 (8 warps),
// 10 tokens per warp, lanes 0-24 load each 50-float row as 25 x float2.
// Tail: per-row arrive-last finalize (scope = 25 blocks, deterministic sum).
// ---------------------------------------------------------------------------
__global__ __launch_bounds__(256)
void fused_gather_kernel(const int* __restrict__ t,
                         const float* __restrict__ emb,
                         const float* __restrict__ W,
                         const float* __restrict__ bias,
                         float* __restrict__ out)
{
    const int b     = blockIdx.x;
    const int chunk = blockIdx.y;
    const int tid   = threadIdx.x;
    const int wid   = tid >> 5;
    const int lane  = tid & 31;

    __shared__ int    sidx[TOK];
    __shared__ float2 sred[WARPS][25];

    const int* tp = t + (size_t)b * SEQ + (size_t)chunk * TOK;
    if (tid < TOK) sidx[tid] = tp[tid];
    __syncthreads();

    const float2* __restrict__ emb2 = (const float2*)emb;

    float2 acc = make_float2(0.0f, 0.0f);
    if (lane < 25) {
        #pragma unroll
        for (int i = 0; i < TOK_PER_WARP; i++) {
            int idx = sidx[wid * TOK_PER_WARP + i];
            if (idx >= 0 && idx < VOCAB) {
                float2 v = __ldg(&emb2[(size_t)idx * 25 + lane]);
                acc.x += v.x;
                acc.y += v.y;
            }
        }
        sred[wid][lane] = acc;
    }
    __syncthreads();

    // Warp 0: reduce 8 warp partials, project onto the two W rows.
    if (tid < 32) {
        float d0 = 0.0f, d1 = 0.0f;
        if (tid < 25) {
            float2 p = make_float2(0.0f, 0.0f);
            #pragma unroll
            for (int w = 0; w < WARPS; w++) {
                p.x += sred[w][tid].x;
                p.y += sred[w][tid].y;
            }
            d0 = p.x * W[2 * tid]       + p.y * W[2 * tid + 1];       // W row 0
            d1 = p.x * W[EMB + 2 * tid] + p.y * W[EMB + 2 * tid + 1]; // W row 1
        }
        #pragma unroll
        for (int off = 16; off > 0; off >>= 1) {
            d0 += __shfl_down_sync(0xFFFFFFFFu, d0, off);
            d1 += __shfl_down_sync(0xFFFFFFFFu, d1, off);
        }

        if (tid == 0) {
            // Publish this chunk's partial (plain store).
            asm volatile("st.global.v2.f32 [%0], {%1, %2};"
                         :: "l"(&g_dots[b][chunk]), "f"(d0), "f"(d1)
                         : "memory");

            // acq_rel arrival: releases my store; if I'm last (old == 24) the
            // RMW also acquires every peer's release -> their stores visible.
            unsigned int old;
            asm volatile("atom.acq_rel.gpu.global.add.u32 %0, [%1], %2;"
                         : "=r"(old)
                         : "l"(&g_cnt[b * 8]), "r"(1u)
                         : "memory");

            if (old == NCHUNK - 1) {
                // Deterministic fixed-order reduction over 25 partials.
                // __ldcg: read at L2 (bypass possibly-stale L1).
                float s0 = 0.0f, s1 = 0.0f;
                #pragma unroll
                for (int k = 0; k < NCHUNK; k++) {
                    float2 p = __ldcg(&g_dots[b][k]);
                    s0 += p.x;
                    s1 += p.y;
                }
                const float inv = 1.0f / (float)BATCH;
                out[b * OUTD + 0] = fmaxf(s0 * inv + bias[0], 0.0f);
                out[b * OUTD + 1] = fmaxf(s1 * inv + bias[1], 0.0f);

                // Reset counter for the next graph replay (launches serialize
                // at the kernel boundary, so no race with the next replay).
                asm volatile("st.global.u32 [%0], %1;"
                             :: "l"(&g_cnt[b * 8]), "r"(0u) : "memory");
            }
        }
    }
}

// ---------------------------------------------------------------------------
// Inputs: t [128,2000] int32, embeddings [1e6,50] f32, W [2,50] f32, b [2] f32.
// Output: [128,2] f32.
// ---------------------------------------------------------------------------
extern "C" void kernel_launch(void* const* d_in, const int* in_sizes, int n_in,
                              void* d_out, int out_size)
{
    const int*   t   = (const int*)d_in[0];
    const float* emb = (const float*)d_in[1];
    const float* W   = (const float*)d_in[2];
    const float* bia = (const float*)d_in[3];
    float*       out = (float*)d_out;

    dim3 grid(BATCH, NCHUNK);
    fused_gather_kernel<<<grid, 256>>>(t, emb, W, bia, out);
}